// round 1
// baseline (speedup 1.0000x reference)
#include <cuda_runtime.h>

#define EPSF 1e-5f

// Problem dims
#define NN  64
#define CC  64
#define TD  300
#define VV  25
#define SS  3
#define ICn 16
#define OCn 64

// Kernel A tiling
#define TTA    4              // t's per subtile
#define TCHUNK 60             // t's per block
#define NCH    5              // TD / TCHUNK
#define COLA   (TTA*VV)       // 100
#define SUBS   (TCHUNK/TTA)   // 15

// Kernel B tiling
#define TTB  5
#define COLB (TTB*VV)         // 125
#define XMS  129              // padded xm row stride (odd -> conflict free)
#define NTB  (TD/TTB)         // 60

// Scratch (static device globals: no runtime allocation)
__device__ float g_Mpart[NCH*NN*SS*VV*VV];   // split-K partials of M
__device__ float g_Aadp [NN*SS*VV*VV];       // adaptive adjacency per (n,s)

// ---------------------------------------------------------------------------
// Kernel A: per (chunk, s, n) block computes partial M[v,w] over 60 t's.
// a = tanh(bn(Wa x)), b = tanh(bn(Wb x)); M += a^T b over (i,t).
// BN folded into weights: w' = w*scale, shift = (bias-mean)*scale+beta.
// ---------------------------------------------------------------------------
__global__ __launch_bounds__(256) void kA(
    const float* __restrict__ x,
    const float* __restrict__ wa, const float* __restrict__ ba,
    const float* __restrict__ wb, const float* __restrict__ bb,
    const float* __restrict__ gag, const float* __restrict__ gab,
    const float* __restrict__ gam, const float* __restrict__ gav,
    const float* __restrict__ gbg, const float* __restrict__ gbb,
    const float* __restrict__ gbm, const float* __restrict__ gbv)
{
    __shared__ float s_wa[ICn*CC];
    __shared__ float s_wb[ICn*CC];
    __shared__ float s_sha[ICn];
    __shared__ float s_shb[ICn];
    __shared__ float s_x[CC*COLA];
    __shared__ float s_a[ICn*COLA];
    __shared__ float s_b[ICn*COLA];

    const int tid  = threadIdx.x;
    const int wid  = tid >> 5;
    const int lane = tid & 31;
    const int chunk = blockIdx.x;
    const int s     = blockIdx.y;
    const int n     = blockIdx.z;

    // Fold BN into weights / shifts
    for (int idx = tid; idx < ICn*CC; idx += 256) {
        int i = idx / CC;
        float sca = gag[s*ICn+i] * rsqrtf(gav[s*ICn+i] + EPSF);
        float scb = gbg[s*ICn+i] * rsqrtf(gbv[s*ICn+i] + EPSF);
        s_wa[idx] = wa[s*ICn*CC + idx] * sca;
        s_wb[idx] = wb[s*ICn*CC + idx] * scb;
    }
    if (tid < ICn) {
        float sca = gag[s*ICn+tid] * rsqrtf(gav[s*ICn+tid] + EPSF);
        float scb = gbg[s*ICn+tid] * rsqrtf(gbv[s*ICn+tid] + EPSF);
        s_sha[tid] = (ba[s*ICn+tid] - gam[s*ICn+tid]) * sca + gab[s*ICn+tid];
        s_shb[tid] = (bb[s*ICn+tid] - gbm[s*ICn+tid]) * scb + gbb[s*ICn+tid];
    }

    // Persistent M accumulators: lane = v, warp owns w = wid + 8q
    float macc[4] = {0.f, 0.f, 0.f, 0.f};

    const float* xbase = x + (size_t)n*(CC*TD*VV) + (size_t)(chunk*TCHUNK)*VV;

    for (int sub = 0; sub < SUBS; sub++) {
        __syncthreads();
        // Load x subtile [C][TTA*V], contiguous 100 floats per c -> float4
        for (int idx = tid; idx < CC*(COLA/4); idx += 256) {
            int c = idx / (COLA/4);
            int j = idx % (COLA/4);
            float4 v4 = *reinterpret_cast<const float4*>(
                xbase + (size_t)c*(TD*VV) + sub*COLA + j*4);
            *reinterpret_cast<float4*>(&s_x[c*COLA + j*4]) = v4;
        }
        __syncthreads();

        // a/b: 128 tasks (isB, i, lt); lane = v.  x loads vector, w broadcast.
        for (int task = wid; task < 2*ICn*TTA; task += 8) {
            int isB = task >> 6;
            int k   = task & 63;
            int i   = k >> 2;      // TTA == 4
            int lt  = k & 3;
            if (lane < VV) {
                const float* wv = isB ? &s_wb[i*CC] : &s_wa[i*CC];
                const float* xp = &s_x[lt*VV + lane];
                float a0 = 0.f, a1 = 0.f, a2 = 0.f, a3 = 0.f;
                #pragma unroll
                for (int c = 0; c < CC; c += 4) {
                    a0 += xp[(c+0)*COLA] * wv[c+0];
                    a1 += xp[(c+1)*COLA] * wv[c+1];
                    a2 += xp[(c+2)*COLA] * wv[c+2];
                    a3 += xp[(c+3)*COLA] * wv[c+3];
                }
                float acc = (isB ? s_shb[i] : s_sha[i]) + ((a0+a1) + (a2+a3));
                float r = tanhf(acc);
                if (isB) s_b[i*COLA + lt*VV + lane] = r;
                else     s_a[i*COLA + lt*VV + lane] = r;
            }
        }
        __syncthreads();

        // M accumulate: K = ICn*TTA = 64; a vector load, b broadcast.
        #pragma unroll 4
        for (int kk = 0; kk < ICn*TTA; kk++) {
            int base = (kk >> 2)*COLA + (kk & 3)*VV;
            float av = (lane < VV) ? s_a[base + lane] : 0.f;
            #pragma unroll
            for (int q = 0; q < 4; q++) {
                int w  = wid + 8*q;
                int we = (w < VV) ? w : 0;
                macc[q] += av * s_b[base + we];
            }
        }
    }

    if (lane < VV) {
        float* mp = &g_Mpart[((size_t)chunk*NN*SS + (size_t)n*SS + s)*(VV*VV)];
        #pragma unroll
        for (int q = 0; q < 4; q++) {
            int w = wid + 8*q;
            if (w < VV) mp[lane*VV + w] = macc[q];
        }
    }
}

// ---------------------------------------------------------------------------
// Kernel A2: reduce split-K partials, A_adp = A + tanh(M/(IC*T)) * alpha
// ---------------------------------------------------------------------------
__global__ void kA2(const float* __restrict__ A, const float* __restrict__ alpha)
{
    int idx = blockIdx.x * 256 + threadIdx.x;
    if (idx >= NN*SS*VV*VV) return;
    float m = 0.f;
    #pragma unroll
    for (int ch = 0; ch < NCH; ch++)
        m += g_Mpart[ch*(NN*SS*VV*VV) + idx];
    g_Aadp[idx] = A[idx % (SS*VV*VV)]
                + tanhf(m * (1.f/(float)(ICn*TD))) * alpha[0];
}

// ---------------------------------------------------------------------------
// Kernel B: per (t-tile, n): for each s: xm = x_tile @ A_adp[n,s]  (K=25),
// then y += WdT[s] @ xm (K=64). Epilogue: BN + bias + residual + ReLU.
// ---------------------------------------------------------------------------
__global__ __launch_bounds__(256) void kB(
    const float* __restrict__ x,
    const float* __restrict__ wd, const float* __restrict__ db,
    const float* __restrict__ bng, const float* __restrict__ bnb,
    const float* __restrict__ bnm, const float* __restrict__ bnv,
    float* __restrict__ out)
{
    extern __shared__ float sm[];
    float* s_x     = sm;                   // CC*COLB  = 8000
    float* s_xm    = s_x  + CC*COLB;       // CC*XMS   = 8256
    float* s_wdT   = s_xm + CC*XMS;        // CC*65    = 4160
    float* s_Aad   = s_wdT + CC*65;        // 640 (padded)
    float* s_scale = s_Aad + 640;          // 64
    float* s_off   = s_scale + 64;         // 64

    const int tid  = threadIdx.x;
    const int wid  = tid >> 5;
    const int lane = tid & 31;
    const int tb = blockIdx.x;
    const int n  = blockIdx.y;
    const int t0 = tb * TTB;

    const float* xb = x + (size_t)n*(CC*TD*VV) + (size_t)t0*VV;

    // Load x tile [C][125] (contiguous 125 per c)
    for (int idx = tid; idx < CC*COLB; idx += 256) {
        int c = idx / COLB, col = idx % COLB;
        s_x[idx] = xb[(size_t)c*(TD*VV) + col];
    }
    // Zero xm incl. pad columns (pad stays 0 forever)
    for (int idx = tid; idx < CC*XMS; idx += 256) s_xm[idx] = 0.f;
    // Epilogue params: scale_o, off_o (absorbs summed conv_d bias + BN)
    if (tid < OCn) {
        float sc = bng[tid] * rsqrtf(bnv[tid] + EPSF);
        float ds = db[tid] + db[OCn + tid] + db[2*OCn + tid];
        s_scale[tid] = sc;
        s_off[tid]   = (ds - bnm[tid]) * sc + bnb[tid];
    }

    float yacc[8][4];
    #pragma unroll
    for (int r = 0; r < 8; r++)
        #pragma unroll
        for (int j = 0; j < 4; j++) yacc[r][j] = 0.f;

    for (int s = 0; s < SS; s++) {
        __syncthreads();   // prior GEMM2 / init done before reloading tiles
        for (int idx = tid; idx < VV*VV; idx += 256)
            s_Aad[idx] = g_Aadp[((size_t)n*SS + s)*(VV*VV) + idx];
        for (int idx = tid; idx < CC*OCn; idx += 256) {
            int o = idx >> 6, c = idx & 63;
            s_wdT[c*65 + o] = wd[s*(OCn*CC) + idx];   // transpose, pad 65
        }
        __syncthreads();

        // GEMM1: xm[c][lt*25+w] = sum_v x[c][lt*25+v] * Aad[v][w]
        // thread: c in {lane, lane+32}; w in {wid+8q}
        for (int lt = 0; lt < TTB; lt++) {
            float acc[2][4];
            #pragma unroll
            for (int q = 0; q < 4; q++) { acc[0][q] = 0.f; acc[1][q] = 0.f; }
            const float* xp0 = &s_x[lane*COLB + lt*VV];
            const float* xp1 = &s_x[(lane+32)*COLB + lt*VV];
            #pragma unroll
            for (int v = 0; v < VV; v++) {
                float x0 = xp0[v], x1 = xp1[v];
                #pragma unroll
                for (int q = 0; q < 4; q++) {
                    int w  = wid + 8*q;
                    int we = (w < VV) ? w : 0;
                    float aa = s_Aad[v*VV + we];
                    acc[0][q] += x0 * aa;
                    acc[1][q] += x1 * aa;
                }
            }
            #pragma unroll
            for (int q = 0; q < 4; q++) {
                int w = wid + 8*q;
                if (w < VV) {
                    s_xm[lane*XMS        + lt*VV + w] = acc[0][q];
                    s_xm[(lane+32)*XMS   + lt*VV + w] = acc[1][q];
                }
            }
        }
        __syncthreads();

        // GEMM2: y[o][col] += sum_c wdT[c][o] * xm[c][col]
        // thread: o = wid*8 + r (r<8, broadcast weights), col = lane + 32j
        #pragma unroll 8
        for (int c = 0; c < CC; c++) {
            float xmv[4];
            #pragma unroll
            for (int j = 0; j < 4; j++)
                xmv[j] = s_xm[c*XMS + lane + 32*j];   // pad cols are 0
            #pragma unroll
            for (int r = 0; r < 8; r++) {
                float wv = s_wdT[c*65 + wid*8 + r];
                #pragma unroll
                for (int j = 0; j < 4; j++)
                    yacc[r][j] += wv * xmv[j];
            }
        }
    }

    // Epilogue: BN + residual + ReLU, coalesced stores
    float* ob = out + (size_t)n*(CC*TD*VV) + (size_t)t0*VV;
    #pragma unroll
    for (int r = 0; r < 8; r++) {
        int o = wid*8 + r;
        float sc = s_scale[o], of = s_off[o];
        #pragma unroll
        for (int j = 0; j < 4; j++) {
            int col = lane + 32*j;
            if (col < COLB) {
                float v = yacc[r][j] * sc + of + s_x[o*COLB + col];
                ob[(size_t)o*(TD*VV) + col] = fmaxf(v, 0.f);
            }
        }
    }
}

// ---------------------------------------------------------------------------
extern "C" void kernel_launch(void* const* d_in, const int* in_sizes, int n_in,
                              void* d_out, int out_size)
{
    const float* x     = (const float*)d_in[0];
    const float* A     = (const float*)d_in[1];
    const float* alpha = (const float*)d_in[2];
    const float* caw   = (const float*)d_in[3];
    const float* cab   = (const float*)d_in[4];
    const float* cbw   = (const float*)d_in[5];
    const float* cbb   = (const float*)d_in[6];
    const float* bag   = (const float*)d_in[7];
    const float* babt  = (const float*)d_in[8];
    const float* bam   = (const float*)d_in[9];
    const float* bav   = (const float*)d_in[10];
    const float* bbg   = (const float*)d_in[11];
    const float* bbbt  = (const float*)d_in[12];
    const float* bbm   = (const float*)d_in[13];
    const float* bbv   = (const float*)d_in[14];
    const float* cdw   = (const float*)d_in[15];
    const float* cdb   = (const float*)d_in[16];
    const float* bng   = (const float*)d_in[17];
    const float* bnb   = (const float*)d_in[18];
    const float* bnm   = (const float*)d_in[19];
    const float* bnv   = (const float*)d_in[20];
    float* out = (float*)d_out;

    const int smemB = (CC*COLB + CC*XMS + CC*65 + 640 + 64 + 64) * sizeof(float);
    cudaFuncSetAttribute(kB, cudaFuncAttributeMaxDynamicSharedMemorySize, smemB);

    kA<<<dim3(NCH, SS, NN), 256>>>(x, caw, cab, cbw, cbb,
                                   bag, babt, bam, bav,
                                   bbg, bbbt, bbm, bbv);
    kA2<<<(NN*SS*VV*VV + 255)/256, 256>>>(A, alpha);
    kB<<<dim3(NTB, NN), 256, smemB>>>(x, cdw, cdb, bng, bnb, bnm, bnv, out);
}

// round 2
// speedup vs baseline: 1.7319x; 1.7319x over previous
#include <cuda_runtime.h>

#define EPSF 1e-5f

// Problem dims
#define NN  64
#define CC  64
#define TD  300
#define VV  25
#define SS  3
#define ICn 16
#define OCn 64

// Kernel A tiling
#define TTA    4              // t's per subtile
#define TCHUNK 60             // t's per block
#define NCH    5              // TD / TCHUNK
#define COLA   (TTA*VV)       // 100
#define SUBS   (TCHUNK/TTA)   // 15
#define ABS_R  28             // padded row stride for s_a/s_b (16B aligned)

// Kernel B tiling
#define TTB  5
#define COLB (TTB*VV)         // 125
#define XMS  132              // padded xm row stride (16B aligned)
#define NTB  (TD/TTB)         // 60
#define XROW 28               // padded per-(c,lt) x row

__device__ float g_Mpart[NCH*NN*SS*VV*VV];
__device__ float g_Aadp [NN*SS*VV*VV];

__device__ __forceinline__ float tanh_fast(float x) {
    float y;
    asm("tanh.approx.f32 %0, %1;" : "=f"(y) : "f"(x));
    return y;
}

// ---------------------------------------------------------------------------
// Kernel A: per (chunk, s, n): a = tanh(bn(Wa x)), b = tanh(bn(Wb x)),
// partial M[v,w] += a^T b over 60 t's. BN folded into weights.
// ---------------------------------------------------------------------------
__global__ __launch_bounds__(256) void kA(
    const float* __restrict__ x,
    const float* __restrict__ wa, const float* __restrict__ ba,
    const float* __restrict__ wb, const float* __restrict__ bb,
    const float* __restrict__ gag, const float* __restrict__ gab,
    const float* __restrict__ gam, const float* __restrict__ gav,
    const float* __restrict__ gbg, const float* __restrict__ gbb,
    const float* __restrict__ gbm, const float* __restrict__ gbv)
{
    __shared__ float s_w[CC*32];          // [c][0..15]=wa', [16..31]=wb'
    __shared__ float s_sha[ICn], s_shb[ICn];
    __shared__ float s_x[CC*COLA];
    __shared__ float s_a[ICn*TTA*ABS_R + 8];
    __shared__ float s_b[ICn*TTA*ABS_R + 8];

    const int tid  = threadIdx.x;
    const int wid  = tid >> 5;
    const int lane = tid & 31;
    const int chunk = blockIdx.x;
    const int s     = blockIdx.y;
    const int n     = blockIdx.z;

    // Fold BN into weights; layout [c][i] interleaved a|b for float2 broadcast
    for (int idx = tid; idx < ICn*CC; idx += 256) {
        int i = idx / CC, c = idx % CC;
        float sca = gag[s*ICn+i] * rsqrtf(gav[s*ICn+i] + EPSF);
        float scb = gbg[s*ICn+i] * rsqrtf(gbv[s*ICn+i] + EPSF);
        s_w[c*32 + i]      = wa[s*ICn*CC + idx] * sca;
        s_w[c*32 + 16 + i] = wb[s*ICn*CC + idx] * scb;
    }
    if (tid < ICn) {
        float sca = gag[s*ICn+tid] * rsqrtf(gav[s*ICn+tid] + EPSF);
        float scb = gbg[s*ICn+tid] * rsqrtf(gbv[s*ICn+tid] + EPSF);
        s_sha[tid] = (ba[s*ICn+tid] - gam[s*ICn+tid]) * sca + gab[s*ICn+tid];
        s_shb[tid] = (bb[s*ICn+tid] - gbm[s*ICn+tid]) * scb + gbb[s*ICn+tid];
    }

    // Persistent M accumulators: lane = v, w = wid*4 + q
    float macc[4] = {0.f, 0.f, 0.f, 0.f};

    const float* xbase = x + (size_t)n*(CC*TD*VV) + (size_t)(chunk*TCHUNK)*VV;

    // conv thread mapping (200 active): 2 i's x 4 cols, both a and b
    const int igrp   = tid / 25;        // 0..7 when active
    const int colgrp = tid - igrp*25;   // 0..24
    const int i0     = igrp*2;
    const bool act   = (tid < 200);

    for (int sub = 0; sub < SUBS; sub++) {
        __syncthreads();
        // Load x subtile [C][100] (float4)
        for (int idx = tid; idx < CC*(COLA/4); idx += 256) {
            int c = idx / (COLA/4);
            int j = idx % (COLA/4);
            float4 v4 = *reinterpret_cast<const float4*>(
                xbase + (size_t)c*(TD*VV) + sub*COLA + j*4);
            *reinterpret_cast<float4*>(&s_x[c*COLA + j*4]) = v4;
        }
        __syncthreads();

        if (act) {
            float acc_a[2][4], acc_b[2][4];
            #pragma unroll
            for (int r = 0; r < 2; r++)
                #pragma unroll
                for (int j = 0; j < 4; j++) { acc_a[r][j] = 0.f; acc_b[r][j] = 0.f; }

            #pragma unroll 8
            for (int c = 0; c < CC; c++) {
                float4 xv = *reinterpret_cast<const float4*>(&s_x[c*COLA + colgrp*4]);
                float2 wA = *reinterpret_cast<const float2*>(&s_w[c*32 + i0]);
                float2 wB = *reinterpret_cast<const float2*>(&s_w[c*32 + 16 + i0]);
                acc_a[0][0] += wA.x*xv.x; acc_a[0][1] += wA.x*xv.y;
                acc_a[0][2] += wA.x*xv.z; acc_a[0][3] += wA.x*xv.w;
                acc_a[1][0] += wA.y*xv.x; acc_a[1][1] += wA.y*xv.y;
                acc_a[1][2] += wA.y*xv.z; acc_a[1][3] += wA.y*xv.w;
                acc_b[0][0] += wB.x*xv.x; acc_b[0][1] += wB.x*xv.y;
                acc_b[0][2] += wB.x*xv.z; acc_b[0][3] += wB.x*xv.w;
                acc_b[1][0] += wB.y*xv.x; acc_b[1][1] += wB.y*xv.y;
                acc_b[1][2] += wB.y*xv.z; acc_b[1][3] += wB.y*xv.w;
            }

            #pragma unroll
            for (int r = 0; r < 2; r++) {
                float sha = s_sha[i0+r], shb = s_shb[i0+r];
                #pragma unroll
                for (int j = 0; j < 4; j++) {
                    int col = colgrp*4 + j;
                    int lt  = col / 25;
                    int v   = col - lt*25;
                    int row = (i0+r)*TTA + lt;
                    s_a[row*ABS_R + v] = tanh_fast(acc_a[r][j] + sha);
                    s_b[row*ABS_R + v] = tanh_fast(acc_b[r][j] + shb);
                }
            }
        }
        __syncthreads();

        // M accumulate: K = 64 rows; a vector load, b broadcast float4
        #pragma unroll 8
        for (int kk = 0; kk < ICn*TTA; kk++) {
            float  av = s_a[kk*ABS_R + lane];
            float4 bv = *reinterpret_cast<const float4*>(&s_b[kk*ABS_R + wid*4]);
            macc[0] += av*bv.x; macc[1] += av*bv.y;
            macc[2] += av*bv.z; macc[3] += av*bv.w;
        }
    }

    if (lane < VV) {
        float* mp = &g_Mpart[((size_t)chunk*NN*SS + (size_t)n*SS + s)*(VV*VV)];
        #pragma unroll
        for (int q = 0; q < 4; q++) {
            int w = wid*4 + q;
            if (w < VV) mp[lane*VV + w] = macc[q];
        }
    }
}

// ---------------------------------------------------------------------------
// Kernel A2: reduce partials, A_adp = A + tanh(M/(IC*T)) * alpha  (precise tanh)
// ---------------------------------------------------------------------------
__global__ void kA2(const float* __restrict__ A, const float* __restrict__ alpha)
{
    int idx = blockIdx.x * 256 + threadIdx.x;
    if (idx >= NN*SS*VV*VV) return;
    float m = 0.f;
    #pragma unroll
    for (int ch = 0; ch < NCH; ch++)
        m += g_Mpart[ch*(NN*SS*VV*VV) + idx];
    g_Aadp[idx] = A[idx % (SS*VV*VV)]
                + tanhf(m * (1.f/(float)(ICn*TD))) * alpha[0];
}

// ---------------------------------------------------------------------------
// Kernel B: per (t-tile, n): for each s: xm = x_tile @ A_adp (K=25),
// y += WdT @ xm (K=64). Epilogue: BN + bias + residual + ReLU.
// ---------------------------------------------------------------------------
__global__ __launch_bounds__(256) void kB(
    const float* __restrict__ x,
    const float* __restrict__ wd, const float* __restrict__ db,
    const float* __restrict__ bng, const float* __restrict__ bnb,
    const float* __restrict__ bnm, const float* __restrict__ bnv,
    float* __restrict__ out)
{
    extern __shared__ float sm[];
    float* s_x     = sm;                    // CC*5*XROW = 8960
    float* s_xm    = s_x   + CC*5*XROW;     // CC*XMS    = 8448
    float* s_wdT   = s_xm  + CC*XMS;        // CC*68     = 4352
    float* s_Aad   = s_wdT + CC*68;         // 28*32     = 896
    float* s_scale = s_Aad + 28*32;         // 64
    float* s_off   = s_scale + 64;          // 64

    const int tid  = threadIdx.x;
    const int wid  = tid >> 5;
    const int lane = tid & 31;
    const int tb = blockIdx.x;
    const int n  = blockIdx.y;
    const int t0 = tb * TTB;

    const float* xb = x + (size_t)n*(CC*TD*VV) + (size_t)t0*VV;

    // x tile: [c][lt][v] padded rows of XROW
    for (int idx = tid; idx < CC*COLB; idx += 256) {
        int c = idx / COLB, col = idx % COLB;
        int lt = col / 25, v = col - lt*25;
        s_x[(c*5 + lt)*XROW + v] = xb[(size_t)c*(TD*VV) + col];
    }
    // zero x pads (v = 25..27) — disjoint addresses from fill, no sync needed
    for (int idx = tid; idx < CC*5*3; idx += 256) {
        int row = idx / 3, p = idx % 3;
        s_x[row*XROW + 25 + p] = 0.f;
    }
    // zero xm (pads stay 0)
    for (int idx = tid; idx < CC*XMS; idx += 256) s_xm[idx] = 0.f;
    // epilogue params
    if (tid < OCn) {
        float sc = bng[tid] * rsqrtf(bnv[tid] + EPSF);
        float ds = db[tid] + db[OCn + tid] + db[2*OCn + tid];
        s_scale[tid] = sc;
        s_off[tid]   = (ds - bnm[tid]) * sc + bnb[tid];
    }

    float yacc[8][4];
    #pragma unroll
    for (int r = 0; r < 8; r++)
        #pragma unroll
        for (int j = 0; j < 4; j++) yacc[r][j] = 0.f;

    for (int s = 0; s < SS; s++) {
        __syncthreads();
        // A_adp padded [28][32], zeros outside 25x25 (single guarded pass)
        for (int idx = tid; idx < 28*32; idx += 256) {
            int v = idx >> 5, w = idx & 31;
            s_Aad[idx] = (v < VV && w < VV)
                       ? g_Aadp[((size_t)n*SS + s)*(VV*VV) + v*VV + w] : 0.f;
        }
        for (int idx = tid; idx < CC*OCn; idx += 256) {
            int o = idx >> 6, c = idx & 63;
            s_wdT[c*68 + o] = wd[s*(OCn*CC) + idx];
        }
        __syncthreads();

        // GEMM1: xm[c][lt*25+w] = sum_v x[c][lt][v]*Aad[v][w]
        // thread: c in {lane, lane+32}, w = wid*4+q
        for (int lt = 0; lt < TTB; lt++) {
            float acc0[4] = {0.f,0.f,0.f,0.f};
            float acc1[4] = {0.f,0.f,0.f,0.f};
            const float* xp0 = &s_x[(lane*5 + lt)*XROW];
            const float* xp1 = &s_x[((lane+32)*5 + lt)*XROW];
            #pragma unroll
            for (int v4 = 0; v4 < 7; v4++) {
                float4 x0 = *reinterpret_cast<const float4*>(xp0 + v4*4);
                float4 x1 = *reinterpret_cast<const float4*>(xp1 + v4*4);
                #pragma unroll
                for (int vv = 0; vv < 4; vv++) {
                    float4 aav = *reinterpret_cast<const float4*>(
                        &s_Aad[(v4*4+vv)*32 + wid*4]);
                    float xs0 = (&x0.x)[vv], xs1 = (&x1.x)[vv];
                    acc0[0] += xs0*aav.x; acc0[1] += xs0*aav.y;
                    acc0[2] += xs0*aav.z; acc0[3] += xs0*aav.w;
                    acc1[0] += xs1*aav.x; acc1[1] += xs1*aav.y;
                    acc1[2] += xs1*aav.z; acc1[3] += xs1*aav.w;
                }
            }
            #pragma unroll
            for (int q = 0; q < 4; q++) {
                int w = wid*4 + q;
                if (w < VV) {
                    s_xm[lane*XMS      + lt*25 + w] = acc0[q];
                    s_xm[(lane+32)*XMS + lt*25 + w] = acc1[q];
                }
            }
        }
        __syncthreads();

        // GEMM2: y[o][col] += sum_c wdT[c][o]*xm[c][col]; col = lane*4+j
        #pragma unroll 8
        for (int c = 0; c < CC; c++) {
            float4 xmv = *reinterpret_cast<const float4*>(&s_xm[c*XMS + lane*4]);
            float4 w0  = *reinterpret_cast<const float4*>(&s_wdT[c*68 + wid*8]);
            float4 w1  = *reinterpret_cast<const float4*>(&s_wdT[c*68 + wid*8 + 4]);
            yacc[0][0] += w0.x*xmv.x; yacc[0][1] += w0.x*xmv.y; yacc[0][2] += w0.x*xmv.z; yacc[0][3] += w0.x*xmv.w;
            yacc[1][0] += w0.y*xmv.x; yacc[1][1] += w0.y*xmv.y; yacc[1][2] += w0.y*xmv.z; yacc[1][3] += w0.y*xmv.w;
            yacc[2][0] += w0.z*xmv.x; yacc[2][1] += w0.z*xmv.y; yacc[2][2] += w0.z*xmv.z; yacc[2][3] += w0.z*xmv.w;
            yacc[3][0] += w0.w*xmv.x; yacc[3][1] += w0.w*xmv.y; yacc[3][2] += w0.w*xmv.z; yacc[3][3] += w0.w*xmv.w;
            yacc[4][0] += w1.x*xmv.x; yacc[4][1] += w1.x*xmv.y; yacc[4][2] += w1.x*xmv.z; yacc[4][3] += w1.x*xmv.w;
            yacc[5][0] += w1.y*xmv.x; yacc[5][1] += w1.y*xmv.y; yacc[5][2] += w1.y*xmv.z; yacc[5][3] += w1.y*xmv.w;
            yacc[6][0] += w1.z*xmv.x; yacc[6][1] += w1.z*xmv.y; yacc[6][2] += w1.z*xmv.z; yacc[6][3] += w1.z*xmv.w;
            yacc[7][0] += w1.w*xmv.x; yacc[7][1] += w1.w*xmv.y; yacc[7][2] += w1.w*xmv.z; yacc[7][3] += w1.w*xmv.w;
        }
    }

    // Epilogue: BN + residual + ReLU
    float* ob = out + (size_t)n*(CC*TD*VV) + (size_t)t0*VV;
    #pragma unroll
    for (int r = 0; r < 8; r++) {
        int o = wid*8 + r;
        float sc = s_scale[o], of = s_off[o];
        #pragma unroll
        for (int j = 0; j < 4; j++) {
            int col = lane*4 + j;
            if (col < COLB) {
                int lt = col / 25, v = col - lt*25;
                float val = yacc[r][j]*sc + of + s_x[(o*5 + lt)*XROW + v];
                ob[(size_t)o*(TD*VV) + col] = fmaxf(val, 0.f);
            }
        }
    }
}

// ---------------------------------------------------------------------------
extern "C" void kernel_launch(void* const* d_in, const int* in_sizes, int n_in,
                              void* d_out, int out_size)
{
    const float* x     = (const float*)d_in[0];
    const float* A     = (const float*)d_in[1];
    const float* alpha = (const float*)d_in[2];
    const float* caw   = (const float*)d_in[3];
    const float* cab   = (const float*)d_in[4];
    const float* cbw   = (const float*)d_in[5];
    const float* cbb   = (const float*)d_in[6];
    const float* bag   = (const float*)d_in[7];
    const float* babt  = (const float*)d_in[8];
    const float* bam   = (const float*)d_in[9];
    const float* bav   = (const float*)d_in[10];
    const float* bbg   = (const float*)d_in[11];
    const float* bbbt  = (const float*)d_in[12];
    const float* bbm   = (const float*)d_in[13];
    const float* bbv   = (const float*)d_in[14];
    const float* cdw   = (const float*)d_in[15];
    const float* cdb   = (const float*)d_in[16];
    const float* bng   = (const float*)d_in[17];
    const float* bnb   = (const float*)d_in[18];
    const float* bnm   = (const float*)d_in[19];
    const float* bnv   = (const float*)d_in[20];
    float* out = (float*)d_out;

    const int smemB = (CC*5*XROW + CC*XMS + CC*68 + 28*32 + 64 + 64) * sizeof(float);
    cudaFuncSetAttribute(kB, cudaFuncAttributeMaxDynamicSharedMemorySize, smemB);

    kA<<<dim3(NCH, SS, NN), 256>>>(x, caw, cab, cbw, cbb,
                                   bag, babt, bam, bav,
                                   bbg, bbbt, bbm, bbv);
    kA2<<<(NN*SS*VV*VV + 255)/256, 256>>>(A, alpha);
    kB<<<dim3(NTB, NN), 256, smemB>>>(x, cdw, cdb, bng, bnb, bnm, bnv, out);
}